// round 3
// baseline (speedup 1.0000x reference)
#include <cuda_runtime.h>
#include <cuda_bf16.h>

// RobustSum L1 IRLS (K=3): x(128,1024) @ W(1024,1024) -> z(128,1024), fp32.
//
// Per (b,o): c = z/D1; iterate with t_i = x_i*W_io - c (single FFMA),
//   r_i = 1/(|t_i|+eps)  [abs folds into FADD operand modifier, rcp = MUFU]
//   q  = sum r_i*t_i, sw = sum r_i   (packed f32x2 accumulators over 2 o's)
//   c' = (q + c*sw) / max(sw, 1e-12)          [since sum r*xw = q + c*sw]
// out = D1 * c.
//
// Parallelism: lane = (iq:2 bits, opair:3 bits); each thread: 1 b, 2 o's,
// 256-i chunk; combine i-chunks with shfl.xor(8), shfl.xor(16).
// Block = 4 warps = 4 b-rows x 16 o's. Grid (64, 32) = 2048 blocks
// -> ~48 warps/SM resident (launch_bounds(128,12) caps regs at 42).
// x smem chunks padded (stride 257) so the 4 iq-groups hit distinct banks.

#define DIN     1024
#define DOUT    1024
#define KITER   3
#define EPSILON 0.001f
#define TBROWS  4
#define OTILE   16
#define ICHUNK  256
#define XPITCH  257       // ICHUNK+1: de-conflicts the 4 iq groups
#define NTHREADS 128

typedef unsigned long long ull;

__device__ __forceinline__ ull pack2(float lo, float hi) {
    ull r; asm("mov.b64 %0, {%1,%2};" : "=l"(r) : "f"(lo), "f"(hi)); return r;
}
__device__ __forceinline__ void unpack2(ull v, float& lo, float& hi) {
    asm("mov.b64 {%0,%1}, %2;" : "=f"(lo), "=f"(hi) : "l"(v));
}
__device__ __forceinline__ ull fma2(ull a, ull b, ull c) {
    ull r; asm("fma.rn.f32x2 %0, %1, %2, %3;" : "=l"(r) : "l"(a), "l"(b), "l"(c)); return r;
}
__device__ __forceinline__ ull add2(ull a, ull b) {
    ull r; asm("add.rn.f32x2 %0, %1, %2;" : "=l"(r) : "l"(a), "l"(b)); return r;
}
__device__ __forceinline__ float rcpf(float a) {
    float r; asm("rcp.approx.f32 %0, %1;" : "=f"(r) : "f"(a)); return r;
}

__global__ __launch_bounds__(NTHREADS, 12)
void robust_sum_kernel(const float* __restrict__ x,
                       const float* __restrict__ w,
                       float* __restrict__ out)
{
    __shared__ float xs[TBROWS][4 * XPITCH];   // ~16 KB, chunk-padded

    const int wid   = threadIdx.x >> 5;        // local b-row
    const int lane  = threadIdx.x & 31;
    const int iq    = lane >> 3;               // i-chunk 0..3
    const int opair = lane & 7;                // 0..7 -> 2 o's each
    const int b     = blockIdx.y * TBROWS + wid;
    const int o0    = blockIdx.x * OTILE + opair * 2;

    // Stage x tile into padded layout: xs[row][iq*XPITCH + i] = x[b, iq*256+i]
    for (int t = threadIdx.x; t < TBROWS * DIN; t += NTHREADS) {
        int row = t >> 10;            // t / 1024
        int col = t & 1023;
        int q   = col >> 8;           // chunk
        int ii  = col & 255;
        xs[row][q * XPITCH + ii] = x[((size_t)blockIdx.y * TBROWS + row) * DIN + col];
    }
    __syncthreads();

    const float* xrow  = &xs[wid][iq * XPITCH];
    const float* wbase = w + (size_t)(iq * ICHUNK) * DOUT + o0;

    // ---- pass 0: z = x @ W, as c = z/DIN ----
    float s0 = 0.f, s1 = 0.f;
    #pragma unroll 4
    for (int i = 0; i < ICHUNK; i++) {
        float  xi = xrow[i];
        float2 wv = __ldg((const float2*)(wbase + (size_t)i * DOUT));
        s0 = fmaf(xi, wv.x, s0);
        s1 = fmaf(xi, wv.y, s1);
    }
    s0 += __shfl_xor_sync(0xffffffffu, s0, 8);
    s0 += __shfl_xor_sync(0xffffffffu, s0, 16);
    s1 += __shfl_xor_sync(0xffffffffu, s1, 8);
    s1 += __shfl_xor_sync(0xffffffffu, s1, 16);
    float c0 = s0 * (1.0f / DIN);
    float c1 = s1 * (1.0f / DIN);

    // ---- K IRLS iterations ----
    #pragma unroll 1
    for (int k = 0; k < KITER; k++) {
        const float nc0 = -c0, nc1 = -c1;
        ull q01 = 0ULL, sw01 = 0ULL;           // packed accumulators (o0,o1)
        #pragma unroll 4
        for (int i = 0; i < ICHUNK; i++) {
            float  xi = xrow[i];
            float2 wv = __ldg((const float2*)(wbase + (size_t)i * DOUT));
            float t0 = fmaf(xi, wv.x, nc0);            // xw - c
            float t1 = fmaf(xi, wv.y, nc1);
            float d0 = fabsf(t0) + EPSILON;            // |t| free as modifier
            float d1 = fabsf(t1) + EPSILON;
            float r0 = rcpf(d0);                       // MUFU.RCP
            float r1 = rcpf(d1);
            ull r01 = pack2(r0, r1);
            ull t01 = pack2(t0, t1);
            q01  = fma2(r01, t01, q01);                // q  += r*t
            sw01 = add2(sw01, r01);                    // sw += r
        }
        float q0, q1, w0, w1;
        unpack2(q01, q0, q1);
        unpack2(sw01, w0, w1);
        q0 += __shfl_xor_sync(0xffffffffu, q0, 8);
        q0 += __shfl_xor_sync(0xffffffffu, q0, 16);
        q1 += __shfl_xor_sync(0xffffffffu, q1, 8);
        q1 += __shfl_xor_sync(0xffffffffu, q1, 16);
        w0 += __shfl_xor_sync(0xffffffffu, w0, 8);
        w0 += __shfl_xor_sync(0xffffffffu, w0, 16);
        w1 += __shfl_xor_sync(0xffffffffu, w1, 8);
        w1 += __shfl_xor_sync(0xffffffffu, w1, 16);
        // c' = (q + c*sw) / max(sw, 1e-12)
        c0 = __fdividef(fmaf(c0, w0, q0), fmaxf(w0, 1e-12f));
        c1 = __fdividef(fmaf(c1, w1, q1), fmaxf(w1, 1e-12f));
    }

    if (iq == 0) {
        float2 res = make_float2((float)DIN * c0, (float)DIN * c1);
        *(float2*)(out + (size_t)b * DOUT + o0) = res;
    }
}

extern "C" void kernel_launch(void* const* d_in, const int* in_sizes, int n_in,
                              void* d_out, int out_size)
{
    const float* x = (const float*)d_in[0];   // (128, 1024)
    const float* w = (const float*)d_in[1];   // (1024, 1024)
    float* out = (float*)d_out;               // (128, 1024)

    dim3 grid(DOUT / OTILE, 128 / TBROWS);    // (64, 32) = 2048 blocks
    robust_sum_kernel<<<grid, NTHREADS>>>(x, w, out);
}

// round 5
// speedup vs baseline: 1.2064x; 1.2064x over previous
#include <cuda_runtime.h>
#include <cuda_bf16.h>

// RobustSum L1 IRLS (K=3): x(128,1024) @ W(1024,1024) -> z(128,1024), fp32.
//
// Per (b,o): c = z/D1; t_i = fma(x_i, W_io, -c); r_i = 1/(|t_i|+eps) [MUFU];
// q = sum r*t, sw = sum r;  c' = (q + c*sw)/max(sw,1e-12);  out = D1*c.
//
// R4 layout (resubmitted after infra failure): block = 256 thr = 8 warps =
// iq(4 i-chunks of 256) x bg(2 b-pairs). Thread owns 2 b-rows x 2 o's x 256
// i's: one float2 weight load serves 4 element-ops (L1 wavefronts/element
// halved vs R1, quartered vs R3), warp loads 256B contiguous (2 wavefronts).
// iq partials combine via an 8KB smem tree in packed f32x2 form.
// Predicted floor: MUFU.RCP ~170k cyc chip-wide.

#define DIN     1024
#define DOUT    1024
#define KITER   3
#define EPSILON 0.001f
#define ICHUNK  256
#define NTHREADS 256

typedef unsigned long long ull;

__device__ __forceinline__ ull pack2(float lo, float hi) {
    ull r; asm("mov.b64 %0, {%1,%2};" : "=l"(r) : "f"(lo), "f"(hi)); return r;
}
__device__ __forceinline__ void unpack2(ull v, float& lo, float& hi) {
    asm("mov.b64 {%0,%1}, %2;" : "=f"(lo), "=f"(hi) : "l"(v));
}
__device__ __forceinline__ ull fma2(ull a, ull b, ull c) {
    ull r; asm("fma.rn.f32x2 %0, %1, %2, %3;" : "=l"(r) : "l"(a), "l"(b), "l"(c)); return r;
}
__device__ __forceinline__ ull add2(ull a, ull b) {
    ull r; asm("add.rn.f32x2 %0, %1, %2;" : "=l"(r) : "l"(a), "l"(b)); return r;
}
__device__ __forceinline__ float rcpf(float a) {
    float r; asm("rcp.approx.f32 %0, %1;" : "=f"(r) : "f"(a)); return r;
}

__global__ __launch_bounds__(NTHREADS, 3)
void robust_sum_kernel(const float* __restrict__ x,
                       const float* __restrict__ w,
                       float* __restrict__ out)
{
    __shared__ float xs[4][DIN];                    // 16 KB: 4 b-rows
    __shared__ ulonglong2 red[4][2][32][2];         // 8 KB: [iq][bg][lane][bt]

    const int tid  = threadIdx.x;
    const int wrp  = tid >> 5;
    const int iq   = wrp >> 1;                      // i-chunk 0..3
    const int bg   = wrp & 1;                       // b-pair within block
    const int lane = tid & 31;
    const int o0   = blockIdx.x * 64 + lane * 2;
    const int b0   = blockIdx.y * 4 + bg * 2;       // this thread: rows b0, b0+1

    // Stage x tile (4 rows x 1024), coalesced float4.
    {
        const float4* src = (const float4*)(x + (size_t)blockIdx.y * 4 * DIN);
        float4*       dst = (float4*)&xs[0][0];
        #pragma unroll
        for (int t = tid; t < 4 * DIN / 4; t += NTHREADS)
            dst[t] = src[t];
    }
    __syncthreads();

    const float* xr0   = &xs[bg * 2 + 0][iq * ICHUNK];
    const float* xr1   = &xs[bg * 2 + 1][iq * ICHUNK];
    const float* wbase = w + (size_t)(iq * ICHUNK) * DOUT + o0;

    // ---- pass 0: z = x @ W (as c = z/DIN) ----
    float s00 = 0.f, s01 = 0.f, s10 = 0.f, s11 = 0.f;
    #pragma unroll 8
    for (int i = 0; i < ICHUNK; i++) {
        float2 wv = __ldg((const float2*)(wbase + (size_t)i * DOUT));
        float xi0 = xr0[i], xi1 = xr1[i];
        s00 = fmaf(xi0, wv.x, s00);
        s01 = fmaf(xi0, wv.y, s01);
        s10 = fmaf(xi1, wv.x, s10);
        s11 = fmaf(xi1, wv.y, s11);
    }
    red[iq][bg][lane][0] = make_ulonglong2(pack2(s00, s01), pack2(s10, s11));
    __syncthreads();
    {
        ull a = 0ULL, b = 0ULL;
        #pragma unroll
        for (int j = 0; j < 4; j++) {
            ulonglong2 v = red[j][bg][lane][0];
            a = add2(a, v.x);
            b = add2(b, v.y);
        }
        unpack2(a, s00, s01);
        unpack2(b, s10, s11);
    }
    float c00 = s00 * (1.0f / DIN), c01 = s01 * (1.0f / DIN);
    float c10 = s10 * (1.0f / DIN), c11 = s11 * (1.0f / DIN);

    // ---- K IRLS iterations ----
    #pragma unroll 1
    for (int k = 0; k < KITER; k++) {
        const float n00 = -c00, n01 = -c01, n10 = -c10, n11 = -c11;
        ull q_0 = 0ULL, w_0 = 0ULL;     // b0: packed (o0,o1) accumulators
        ull q_1 = 0ULL, w_1 = 0ULL;     // b1
        #pragma unroll 8
        for (int i = 0; i < ICHUNK; i++) {
            float2 wv = __ldg((const float2*)(wbase + (size_t)i * DOUT));
            float xi0 = xr0[i], xi1 = xr1[i];
            // b0
            float t0 = fmaf(xi0, wv.x, n00);
            float t1 = fmaf(xi0, wv.y, n01);
            float r0 = rcpf(fabsf(t0) + EPSILON);
            float r1 = rcpf(fabsf(t1) + EPSILON);
            ull r01 = pack2(r0, r1);
            q_0 = fma2(r01, pack2(t0, t1), q_0);
            w_0 = add2(w_0, r01);
            // b1
            float u0 = fmaf(xi1, wv.x, n10);
            float u1 = fmaf(xi1, wv.y, n11);
            float p0 = rcpf(fabsf(u0) + EPSILON);
            float p1 = rcpf(fabsf(u1) + EPSILON);
            ull p01 = pack2(p0, p1);
            q_1 = fma2(p01, pack2(u0, u1), q_1);
            w_1 = add2(w_1, p01);
        }
        __syncthreads();                // previous reduce reads done
        red[iq][bg][lane][0] = make_ulonglong2(q_0, w_0);
        red[iq][bg][lane][1] = make_ulonglong2(q_1, w_1);
        __syncthreads();
        ull qa = 0ULL, wa = 0ULL, qb = 0ULL, wb = 0ULL;
        #pragma unroll
        for (int j = 0; j < 4; j++) {
            ulonglong2 v0 = red[j][bg][lane][0];
            ulonglong2 v1 = red[j][bg][lane][1];
            qa = add2(qa, v0.x);  wa = add2(wa, v0.y);
            qb = add2(qb, v1.x);  wb = add2(wb, v1.y);
        }
        float q0f, q1f, w0f, w1f;
        unpack2(qa, q0f, q1f); unpack2(wa, w0f, w1f);
        c00 = __fdividef(fmaf(c00, w0f, q0f), fmaxf(w0f, 1e-12f));
        c01 = __fdividef(fmaf(c01, w1f, q1f), fmaxf(w1f, 1e-12f));
        unpack2(qb, q0f, q1f); unpack2(wb, w0f, w1f);
        c10 = __fdividef(fmaf(c10, w0f, q0f), fmaxf(w0f, 1e-12f));
        c11 = __fdividef(fmaf(c11, w1f, q1f), fmaxf(w1f, 1e-12f));
    }

    if (iq == 0) {
        *(float2*)(out + (size_t)(b0 + 0) * DOUT + o0) =
            make_float2((float)DIN * c00, (float)DIN * c01);
        *(float2*)(out + (size_t)(b0 + 1) * DOUT + o0) =
            make_float2((float)DIN * c10, (float)DIN * c11);
    }
}

extern "C" void kernel_launch(void* const* d_in, const int* in_sizes, int n_in,
                              void* d_out, int out_size)
{
    const float* x = (const float*)d_in[0];   // (128, 1024)
    const float* w = (const float*)d_in[1];   // (1024, 1024)
    float* out = (float*)d_out;               // (128, 1024)

    dim3 grid(DOUT / 64, 128 / 4);            // (16, 32) = 512 blocks
    robust_sum_kernel<<<grid, NTHREADS>>>(x, w, out);
}

// round 6
// speedup vs baseline: 1.3026x; 1.0798x over previous
#include <cuda_runtime.h>
#include <cuda_bf16.h>

// RobustSum L1 IRLS (K=3): x(128,1024) @ W(1024,1024) -> z(128,1024), fp32.
//
// Per (b,o): c = z/D1; t_i = fma(x_i, W_io, -c); r_i = 1/(|t_i|+eps) [MUFU];
// q = sum r*t, sw = sum r;  c' = (q + c*sw)/max(sw,1e-12);  out = D1*c.
//
// R6: block = 128 thr = 4 warps, warp == i-chunk (iq 0..3, 256 i each).
// Block covers 2 b-rows x 64 o; thread owns 2b x 2o x 256i (weight float2
// load serves 4 element-ops; warp loads 256B contiguous = 2 L1 wavefronts).
// Grid (16,64) = 1024 blocks; launch_bounds(128,8) caps regs at 64 so the
// whole grid fits in ONE wave (~7 CTAs/SM, balance 1.01) — kills the R4
// 1.15-wave tail. iq partials combine via 4KB smem tree (packed f32x2).
// Floor: MUFU.RCP ~170k cyc chip-wide (~95us).

#define DIN     1024
#define DOUT    1024
#define KITER   3
#define EPSILON 0.001f
#define ICHUNK  256
#define NTHREADS 128

typedef unsigned long long ull;

__device__ __forceinline__ ull pack2(float lo, float hi) {
    ull r; asm("mov.b64 %0, {%1,%2};" : "=l"(r) : "f"(lo), "f"(hi)); return r;
}
__device__ __forceinline__ void unpack2(ull v, float& lo, float& hi) {
    asm("mov.b64 {%0,%1}, %2;" : "=f"(lo), "=f"(hi) : "l"(v));
}
__device__ __forceinline__ ull fma2(ull a, ull b, ull c) {
    ull r; asm("fma.rn.f32x2 %0, %1, %2, %3;" : "=l"(r) : "l"(a), "l"(b), "l"(c)); return r;
}
__device__ __forceinline__ ull add2(ull a, ull b) {
    ull r; asm("add.rn.f32x2 %0, %1, %2;" : "=l"(r) : "l"(a), "l"(b)); return r;
}
__device__ __forceinline__ float rcpf(float a) {
    float r; asm("rcp.approx.f32 %0, %1;" : "=f"(r) : "f"(a)); return r;
}

__global__ __launch_bounds__(NTHREADS, 8)
void robust_sum_kernel(const float* __restrict__ x,
                       const float* __restrict__ w,
                       float* __restrict__ out)
{
    __shared__ float xs[2][DIN];                 // 8 KB: 2 b-rows
    __shared__ ulonglong2 red[4][2][32];         // 4 KB: [iq][bt][lane]

    const int tid  = threadIdx.x;
    const int iq   = tid >> 5;                   // warp == i-chunk 0..3
    const int lane = tid & 31;
    const int o0   = blockIdx.x * 64 + lane * 2;
    const int b0   = blockIdx.y * 2;             // thread handles rows b0, b0+1

    // Stage x tile (2 rows x 1024), coalesced float4: 128 thr x 4 each.
    {
        const float4* src = (const float4*)(x + (size_t)b0 * DIN);
        float4*       dst = (float4*)&xs[0][0];
        #pragma unroll
        for (int t = tid; t < 2 * DIN / 4; t += NTHREADS)
            dst[t] = src[t];
    }
    __syncthreads();

    const float* xr0   = &xs[0][iq * ICHUNK];
    const float* xr1   = &xs[1][iq * ICHUNK];
    const float* wbase = w + (size_t)(iq * ICHUNK) * DOUT + o0;

    // ---- pass 0: z = x @ W (as c = z/DIN) ----
    float s00 = 0.f, s01 = 0.f, s10 = 0.f, s11 = 0.f;
    #pragma unroll 4
    for (int i = 0; i < ICHUNK; i++) {
        float2 wv = __ldg((const float2*)(wbase + (size_t)i * DOUT));
        float xi0 = xr0[i], xi1 = xr1[i];
        s00 = fmaf(xi0, wv.x, s00);
        s01 = fmaf(xi0, wv.y, s01);
        s10 = fmaf(xi1, wv.x, s10);
        s11 = fmaf(xi1, wv.y, s11);
    }
    red[iq][0][lane] = make_ulonglong2(pack2(s00, s01), pack2(s10, s11));
    __syncthreads();
    {
        ull a = 0ULL, b = 0ULL;
        #pragma unroll
        for (int j = 0; j < 4; j++) {
            ulonglong2 v = red[j][0][lane];
            a = add2(a, v.x);
            b = add2(b, v.y);
        }
        unpack2(a, s00, s01);
        unpack2(b, s10, s11);
    }
    float c00 = s00 * (1.0f / DIN), c01 = s01 * (1.0f / DIN);
    float c10 = s10 * (1.0f / DIN), c11 = s11 * (1.0f / DIN);

    // ---- K IRLS iterations ----
    #pragma unroll 1
    for (int k = 0; k < KITER; k++) {
        const float n00 = -c00, n01 = -c01, n10 = -c10, n11 = -c11;
        ull q_0 = 0ULL, w_0 = 0ULL;      // b0: packed (o0,o1) accumulators
        ull q_1 = 0ULL, w_1 = 0ULL;      // b1
        #pragma unroll 4
        for (int i = 0; i < ICHUNK; i++) {
            float2 wv = __ldg((const float2*)(wbase + (size_t)i * DOUT));
            float xi0 = xr0[i], xi1 = xr1[i];
            // b0
            float t0 = fmaf(xi0, wv.x, n00);
            float t1 = fmaf(xi0, wv.y, n01);
            float r0 = rcpf(fabsf(t0) + EPSILON);
            float r1 = rcpf(fabsf(t1) + EPSILON);
            ull r01 = pack2(r0, r1);
            q_0 = fma2(r01, pack2(t0, t1), q_0);
            w_0 = add2(w_0, r01);
            // b1
            float u0 = fmaf(xi1, wv.x, n10);
            float u1 = fmaf(xi1, wv.y, n11);
            float p0 = rcpf(fabsf(u0) + EPSILON);
            float p1 = rcpf(fabsf(u1) + EPSILON);
            ull p01 = pack2(p0, p1);
            q_1 = fma2(p01, pack2(u0, u1), q_1);
            w_1 = add2(w_1, p01);
        }
        __syncthreads();                 // previous reduce reads done
        red[iq][0][lane] = make_ulonglong2(q_0, w_0);
        red[iq][1][lane] = make_ulonglong2(q_1, w_1);
        __syncthreads();
        ull qa = 0ULL, wa = 0ULL, qb = 0ULL, wb = 0ULL;
        #pragma unroll
        for (int j = 0; j < 4; j++) {
            ulonglong2 v0 = red[j][0][lane];
            ulonglong2 v1 = red[j][1][lane];
            qa = add2(qa, v0.x);  wa = add2(wa, v0.y);
            qb = add2(qb, v1.x);  wb = add2(wb, v1.y);
        }
        float q0f, q1f, w0f, w1f;
        unpack2(qa, q0f, q1f); unpack2(wa, w0f, w1f);
        c00 = __fdividef(fmaf(c00, w0f, q0f), fmaxf(w0f, 1e-12f));
        c01 = __fdividef(fmaf(c01, w1f, q1f), fmaxf(w1f, 1e-12f));
        unpack2(qb, q0f, q1f); unpack2(wb, w0f, w1f);
        c10 = __fdividef(fmaf(c10, w0f, q0f), fmaxf(w0f, 1e-12f));
        c11 = __fdividef(fmaf(c11, w1f, q1f), fmaxf(w1f, 1e-12f));
    }

    if (iq == 0) {
        *(float2*)(out + (size_t)(b0 + 0) * DOUT + o0) =
            make_float2((float)DIN * c00, (float)DIN * c01);
        *(float2*)(out + (size_t)(b0 + 1) * DOUT + o0) =
            make_float2((float)DIN * c10, (float)DIN * c11);
    }
}

extern "C" void kernel_launch(void* const* d_in, const int* in_sizes, int n_in,
                              void* d_out, int out_size)
{
    const float* x = (const float*)d_in[0];   // (128, 1024)
    const float* w = (const float*)d_in[1];   // (1024, 1024)
    float* out = (float*)d_out;               // (128, 1024)

    dim3 grid(DOUT / 64, 128 / 2);            // (16, 64) = 1024 blocks
    robust_sum_kernel<<<grid, NTHREADS>>>(x, w, out);
}